// round 13
// baseline (speedup 1.0000x reference)
#include <cuda_runtime.h>

// SoftmaxProbs: mean = (1/B) * sum_{b,c} l[b,c] * (lse_b - x[b,c])
// 2M rows x 18 classes fp32, HBM-bound (288 MB).
// Warp-owned cp.async double-buffered x staging. Labels streamed with batched
// LDG.128 issued at the TOP of each chunk round (overlapped with LSE phase),
// consumed at the end -> label latency hidden inside the round.
// Uniform full-chunk main region + fine-grained 16-row tail slices.

#define NC 18
#define BLK 256
#define NWARP (BLK / 32)
#define RPW 32                        // rows per warp per main chunk
#define WF  (RPW * NC)                // 576 floats
#define WV4 (WF / 4)                  // 144 float4
#define TRPW 16                       // tail slice rows
#define MAX_GRID 2048

__device__ double       g_partials[MAX_GRID];
__device__ unsigned int g_count = 0;

__device__ __forceinline__ void cpa16(unsigned int saddr, const float4* g) {
    asm volatile("cp.async.cg.shared.global [%0], [%1], 16;" :: "r"(saddr), "l"(g));
}
__device__ __forceinline__ void cpa_commit() {
    asm volatile("cp.async.commit_group;");
}

__global__ __launch_bounds__(BLK, 4)
void ce_main_kernel(const float* __restrict__ x,
                    const float* __restrict__ lab,
                    float* __restrict__ out,
                    int B, int nchunks_main)
{
    __shared__ float  sx[2][NWARP][WF];     // 36864 B
    __shared__ float  rowlse[NWARP][RPW];   // 1024 B
    __shared__ double sred[NWARP];
    __shared__ int    s_last;

    const int tid  = threadIdx.x;
    const int w    = tid >> 5;
    const int lane = tid & 31;

    // Stage this warp's full 32-row slice of chunk c (main region: always full).
    auto stage_full = [&](int c, int s) {
        const long long r0 = (long long)c * BLK + (long long)w * RPW;
        const float4* xb4 = (const float4*)(x + r0 * NC);
        const unsigned sxa = (unsigned)__cvta_generic_to_shared(&sx[s][w][0]);
        #pragma unroll
        for (int j = 0; j < 4; j++)
            cpa16(sxa + (lane + j * 32) * 16, xb4 + lane + j * 32);
        if (lane < WV4 - 128)                       // last 16 float4: lanes 0..15
            cpa16(sxa + (lane + 128) * 16, xb4 + lane + 128);
    };

    // Register-light per-row LSE (two streaming passes over smem), rows <= 32.
    auto lse_phase = [&](const float* sxw, int wr) {
        if (lane < wr) {
            const float2* rx2 = (const float2*)(sxw + lane * NC);  // 8B aligned
            float2 v = rx2[0];
            float m = fmaxf(v.x, v.y);
            #pragma unroll
            for (int k = 1; k < NC / 2; k++) {
                v = rx2[k];
                m = fmaxf(m, fmaxf(v.x, v.y));
            }
            float s = 0.f;
            #pragma unroll
            for (int k = 0; k < NC / 2; k++) {
                v = rx2[k];
                s += __expf(v.x - m) + __expf(v.y - m);
            }
            rowlse[w][lane] = m + __logf(s);
        }
        __syncwarp();
    };

    const int c0 = blockIdx.x;
    double acc = 0.0;

    if (c0 < nchunks_main) stage_full(c0, 0);
    cpa_commit();

    int stg = 0;
    for (int c = c0; c < nchunks_main; c += gridDim.x, stg ^= 1) {
        asm volatile("cp.async.wait_group 0;");     // x(c) resident in sx[stg]
        __syncwarp();

        const long long r0 = (long long)c * BLK + (long long)w * RPW;
        const float4* lb4 = (const float4*)(lab + r0 * NC);

        // ── Hoisted label loads: in flight during stage + LSE phase ──
        float4 L0 = lb4[lane      ];
        float4 L1 = lb4[lane +  32];
        float4 L2 = lb4[lane +  64];
        float4 L3 = lb4[lane +  96];
        float4 L4;
        const bool has5 = lane < (WV4 - 128);       // lanes 0..15
        if (has5) L4 = lb4[lane + 128];

        // ── Stage next chunk's x ──
        const int nxt = c + gridDim.x;
        if (nxt < nchunks_main) stage_full(nxt, stg ^ 1);
        cpa_commit();

        // ── Phase 1: per-row LSE (72 B stride LDS: conflict-free) ──
        float* sxw = &sx[stg][w][0];
        lse_phase(sxw, RPW);

        // ── Phase 2: consume labels (arrived during phase 1) ──
        float f0 = 0.f, f1 = 0.f, f2 = 0.f, f3 = 0.f;
        const float4* sxv = (const float4*)sxw;

        auto consume = [&](float4 lv, int i) {
            const float4 xv = sxv[i];
            const int e = i << 2;
            f0 += lv.x * (rowlse[w][(e    ) / NC] - xv.x);
            f1 += lv.y * (rowlse[w][(e + 1) / NC] - xv.y);
            f2 += lv.z * (rowlse[w][(e + 2) / NC] - xv.z);
            f3 += lv.w * (rowlse[w][(e + 3) / NC] - xv.w);
        };
        consume(L0, lane      );
        consume(L1, lane +  32);
        consume(L2, lane +  64);
        consume(L3, lane +  96);
        if (has5) consume(L4, lane + 128);

        acc += (double)((f0 + f1) + (f2 + f3));
        __syncwarp();                               // slice reusable for restage
    }
    asm volatile("cp.async.wait_group 0;");
    __syncwarp();

    // ── Fine-grained tail: 16-row slices over all warps (static, balanced) ──
    {
        const long long tail_row0 = (long long)nchunks_main * BLK;
        const long long tailrows  = (long long)B - tail_row0;
        if (tailrows > 0) {
            const int ntslices = (int)((tailrows + TRPW - 1) / TRPW);
            const int GW = gridDim.x * NWARP;
            float* sxw = &sx[0][w][0];
            for (int ts = blockIdx.x * NWARP + w; ts < ntslices; ts += GW) {
                const long long r0 = tail_row0 + (long long)ts * TRPW;
                long long rem = (long long)B - r0;
                const int wr = rem < TRPW ? (int)rem : TRPW;
                const float* xb = x + r0 * NC;
                const int nf = wr * NC;
                for (int i = lane; i < nf; i += 32) sxw[i] = xb[i];
                __syncwarp();

                lse_phase(sxw, wr);

                float f0 = 0.f;
                const float* lb = lab + r0 * NC;
                for (int i = lane; i < nf; i += 32)
                    f0 += lb[i] * (rowlse[w][i / NC] - sxw[i]);
                acc += (double)f0;
                __syncwarp();
            }
        }
    }

    // ── per-warp then per-block deterministic reduction ──
    #pragma unroll
    for (int o = 16; o > 0; o >>= 1)
        acc += __shfl_down_sync(0xffffffffu, acc, o);
    if (lane == 0) sred[w] = acc;
    __syncthreads();

    if (tid == 0) {
        double v = 0.0;
        #pragma unroll
        for (int i = 0; i < NWARP; i++) v += sred[i];
        g_partials[blockIdx.x] = v;
        __threadfence();
        unsigned prev = atomicAdd(&g_count, 1u);
        s_last = (prev == gridDim.x - 1u) ? 1 : 0;
    }
    __syncthreads();

    // ── fused finalize: last block sums all partials ──
    if (s_last) {
        double v = 0.0;
        for (int i = tid; i < (int)gridDim.x; i += BLK)
            v += g_partials[i];
        #pragma unroll
        for (int o = 16; o > 0; o >>= 1)
            v += __shfl_down_sync(0xffffffffu, v, o);
        if (lane == 0) sred[w] = v;
        __syncthreads();
        if (tid == 0) {
            double t = 0.0;
            #pragma unroll
            for (int i = 0; i < NWARP; i++) t += sred[i];
            out[0] = (float)(t / (double)B);
            g_count = 0;                            // reset for next graph replay
        }
    }
}

extern "C" void kernel_launch(void* const* d_in, const int* in_sizes, int n_in,
                              void* d_out, int out_size)
{
    const float* x   = (const float*)d_in[0];   // output       [B, 18]
    const float* lab = (const float*)d_in[1];   // labels_soft  [B, 18]
    const int B = in_sizes[0] / NC;
    const int nchunks = (B + BLK - 1) / BLK;

    int grid = 148 * 4;                 // 4 blocks/SM (37 KB smem each)
    if (grid > nchunks) grid = nchunks;
    if (grid < 1) grid = 1;
    if (grid > MAX_GRID) grid = MAX_GRID;

    // Uniform, fully-in-bounds main region (multiple of grid); remainder as
    // fine-grained 16-row tail slices.
    int nchunks_main = (nchunks / grid) * grid;
    while ((long long)nchunks_main * BLK > (long long)B)   // keep main region full
        nchunks_main -= grid;
    if (nchunks_main < 0) nchunks_main = 0;

    ce_main_kernel<<<grid, BLK>>>(x, lab, (float*)d_out, B, nchunks_main);
}